// round 3
// baseline (speedup 1.0000x reference)
#include <cuda_runtime.h>

#define NB 512
#define NT 2048
#define NK 8
#define ND 32
#define DTC 0.05f
#define SQDT 0.22360679774997896f  // sqrt(0.05)

// packed fp32x2 FMA (Blackwell-only; ptxas will not auto-fuse this)
__device__ __forceinline__ unsigned long long ffma2(unsigned long long a,
                                                    unsigned long long b,
                                                    unsigned long long c) {
    unsigned long long d;
    asm("fma.rn.f32x2 %0, %1, %2, %3;" : "=l"(d) : "l"(a), "l"(b), "l"(c));
    return d;
}
__device__ __forceinline__ float2 unpack2(unsigned long long v) {
    float2 r;
    asm("mov.b64 {%0, %1}, %2;" : "=f"(r.x), "=f"(r.y) : "l"(v));
    return r;
}

__global__ void __launch_bounds__(64, 1)
slds_scan_kernel(const float* __restrict__ z0,
                 const float* __restrict__ s_probs,  // [T,B,K]
                 const float* __restrict__ noise,    // [T,B,D]
                 const float* __restrict__ A_s,      // [K,D,D]
                 const float* __restrict__ b_s,      // [K,D]
                 const float* __restrict__ Q_chol,   // [K,D]
                 float* __restrict__ ys)             // [T,B,D]
{
    __shared__ float sm_p[2][ND];
    __shared__ __align__(16) float sm_z[ND];

    const int b   = blockIdx.x;      // batch
    const int tid = threadIdx.x;
    const int h   = tid >> 5;        // warp half: k in [4h, 4h+4)
    const int i   = tid & 31;        // output dim
    const int k0  = h * 4;

    // ---- A rows for this (half-k, i) into registers as f32x2 pairs along j ----
    unsigned long long A2[4][16];
#pragma unroll
    for (int kk = 0; kk < 4; kk++) {
        const ulonglong2* row =
            reinterpret_cast<const ulonglong2*>(A_s + ((size_t)(k0 + kk) * ND + i) * ND);
#pragma unroll
        for (int m = 0; m < 8; m++) {
            ulonglong2 v = row[m];
            A2[kk][2 * m + 0] = v.x;
            A2[kk][2 * m + 1] = v.y;
        }
    }
    float breg[4];
#pragma unroll
    for (int kk = 0; kk < 4; kk++) breg[kk] = b_s[(k0 + kk) * ND + i];
    float Qreg[8];
#pragma unroll
    for (int k = 0; k < 8; k++) Qreg[k] = Q_chol[k * ND + i];

    // ---- initial state ----
    float z = z0[(size_t)b * ND + i];
    sm_z[i] = z;   // both warps write identical value: benign
    __syncthreads();
    unsigned long long z2[16];
#pragma unroll
    for (int m = 0; m < 16; m++)
        z2[m] = reinterpret_cast<const unsigned long long*>(sm_z)[m];

    const float* wp = s_probs + (size_t)b * NK;
    const float* np = noise   + (size_t)b * ND + i;
    float*       yp = ys      + (size_t)b * ND + i;

    // preload t = 0
    float4 wa = *reinterpret_cast<const float4*>(wp);
    float4 wb = *reinterpret_cast<const float4*>(wp + 4);
    float  nz = *np;

    for (int t = 0; t < NT; t++) {
        // ---- software prefetch for t+1 (clamped; hides DRAM latency) ----
        const int tn = (t + 1 < NT) ? (t + 1) : t;
        const float4 wan = *reinterpret_cast<const float4*>(wp + (size_t)tn * NB * NK);
        const float4 wbn = *reinterpret_cast<const float4*>(wp + (size_t)tn * NB * NK + 4);
        const float  nzn = np[(size_t)tn * NB * ND];

        // ---- 4 dot products (this warp's k-half), packed f32x2 ----
        unsigned long long acc0 = 0ull, acc1 = 0ull, acc2 = 0ull, acc3 = 0ull;
#pragma unroll
        for (int m = 0; m < 16; m++) {
            acc0 = ffma2(A2[0][m], z2[m], acc0);
            acc1 = ffma2(A2[1][m], z2[m], acc1);
            acc2 = ffma2(A2[2][m], z2[m], acc2);
            acc3 = ffma2(A2[3][m], z2[m], acc3);
        }
        float2 d0 = unpack2(acc0), d1 = unpack2(acc1);
        float2 d2 = unpack2(acc2), d3 = unpack2(acc3);
        const float dot0 = d0.x + d0.y;
        const float dot1 = d1.x + d1.y;
        const float dot2 = d2.x + d2.y;
        const float dot3 = d3.x + d3.y;

        const float wsum = ((wa.x + wa.y) + (wa.z + wa.w)) +
                           ((wb.x + wb.y) + (wb.z + wb.w));
        const float inv = __fdividef(1.0f, wsum);

        // this warp's 4 weights (warp-uniform branch)
        float wk0, wk1, wk2, wk3;
        if (h == 0) { wk0 = wa.x; wk1 = wa.y; wk2 = wa.z; wk3 = wa.w; }
        else        { wk0 = wb.x; wk1 = wb.y; wk2 = wb.z; wk3 = wb.w; }

        const float p = wk0 * (dot0 + breg[0]) + wk1 * (dot1 + breg[1]) +
                        wk2 * (dot2 + breg[2]) + wk3 * (dot3 + breg[3]);

        // full diffusion term (redundant per warp, cheap)
        const float q = wa.x * Qreg[0] + wa.y * Qreg[1] + wa.z * Qreg[2] + wa.w * Qreg[3] +
                        wb.x * Qreg[4] + wb.y * Qreg[5] + wb.z * Qreg[6] + wb.w * Qreg[7];

        // ---- cross-warp combine of k-halves ----
        sm_p[h][i] = p;
        __syncthreads();
        const float psum = p + sm_p[1 - h][i];   // fp-commutative: both warps identical

        z = z + (DTC * inv) * psum + (q * inv) * (SQDT * nz);

        yp[(size_t)t * NB * ND] = z;

        // ---- broadcast new z to both warps ----
        sm_z[i] = z;  // identical value from both warps
        __syncthreads();
#pragma unroll
        for (int m = 0; m < 16; m++)
            z2[m] = reinterpret_cast<const unsigned long long*>(sm_z)[m];

        wa = wan; wb = wbn; nz = nzn;
    }
}

extern "C" void kernel_launch(void* const* d_in, const int* in_sizes, int n_in,
                              void* d_out, int out_size) {
    const float* z0      = (const float*)d_in[0];
    const float* s_probs = (const float*)d_in[1];
    const float* noise   = (const float*)d_in[2];
    const float* A_s     = (const float*)d_in[3];
    const float* b_s     = (const float*)d_in[4];
    const float* Q_chol  = (const float*)d_in[5];
    float* ys = (float*)d_out;

    slds_scan_kernel<<<NB, 64>>>(z0, s_probs, noise, A_s, b_s, Q_chol, ys);
}

// round 4
// speedup vs baseline: 1.6171x; 1.6171x over previous
#include <cuda_runtime.h>
#include <cstdint>

#define NB 512
#define NT 2048
#define NK 8
#define ND 32
#define DTC 0.05f
#define SQDT 0.22360679774997896f  // sqrt(0.05)
#define PF 6                        // prefetch distance (steps)
#define RING 8                      // smem ring slots (power of 2, > PF+1)

// packed fp32x2 FMA (Blackwell-only; ptxas will not auto-fuse this)
__device__ __forceinline__ unsigned long long ffma2(unsigned long long a,
                                                    unsigned long long b,
                                                    unsigned long long c) {
    unsigned long long d;
    asm("fma.rn.f32x2 %0, %1, %2, %3;" : "=l"(d) : "l"(a), "l"(b), "l"(c));
    return d;
}
__device__ __forceinline__ float2 unpack2(unsigned long long v) {
    float2 r;
    asm("mov.b64 {%0, %1}, %2;" : "=f"(r.x), "=f"(r.y) : "l"(v));
    return r;
}
__device__ __forceinline__ void cp16(uint32_t saddr, const void* gaddr) {
    asm volatile("cp.async.ca.shared.global [%0], [%1], 16;"
                 :: "r"(saddr), "l"(gaddr) : "memory");
}

__global__ void __launch_bounds__(64, 1)
slds_scan_kernel(const float* __restrict__ z0,
                 const float* __restrict__ s_probs,  // [T,B,K]
                 const float* __restrict__ noise,    // [T,B,D]
                 const float* __restrict__ A_s,      // [K,D,D]
                 const float* __restrict__ b_s,      // [K,D]
                 const float* __restrict__ Q_chol,   // [K,D]
                 float* __restrict__ ys)             // [T,B,D]
{
    __shared__ __align__(16) float sm_w[RING][8];    // weights ring
    __shared__ __align__(16) float sm_n[RING][ND];   // noise ring
    __shared__ float sm_p[2][ND];                    // cross-warp p exchange
    __shared__ __align__(16) float sm_z[2][ND];      // per-warp z broadcast

    const int b   = blockIdx.x;
    const int tid = threadIdx.x;
    const int h   = tid >> 5;     // warp: k in [4h, 4h+4)
    const int i   = tid & 31;     // output dim
    const int k0  = h * 4;

    // ---- A rows for this (k-half, i) into registers as f32x2 pairs ----
    unsigned long long A2[4][16];
#pragma unroll
    for (int kk = 0; kk < 4; kk++) {
        const ulonglong2* row =
            reinterpret_cast<const ulonglong2*>(A_s + ((size_t)(k0 + kk) * ND + i) * ND);
#pragma unroll
        for (int m = 0; m < 8; m++) {
            ulonglong2 v = row[m];
            A2[kk][2 * m + 0] = v.x;
            A2[kk][2 * m + 1] = v.y;
        }
    }
    float breg[4];
#pragma unroll
    for (int kk = 0; kk < 4; kk++) breg[kk] = b_s[(k0 + kk) * ND + i];
    float Qreg[8];
#pragma unroll
    for (int k = 0; k < 8; k++) Qreg[k] = Q_chol[k * ND + i];

    // ---- prefetch ring setup (warp 0 only issues; commits keep group counts) ----
    const uint32_t s_n = (uint32_t)__cvta_generic_to_shared(&sm_n[0][0]);
    const uint32_t s_w = (uint32_t)__cvta_generic_to_shared(&sm_w[0][0]);
    const float* gn = noise   + (size_t)b * ND;
    const float* gw = s_probs + (size_t)b * NK;

    if (h == 0) {
#pragma unroll
        for (int s = 0; s < PF; s++) {
            if (i < 8)
                cp16(s_n + (uint32_t)(s * ND + i * 4) * 4,
                     gn + (size_t)s * NB * ND + i * 4);
            else if (i < 10)
                cp16(s_w + (uint32_t)(s * 8 + (i - 8) * 4) * 4,
                     gw + (size_t)s * NB * NK + (i - 8) * 4);
            asm volatile("cp.async.commit_group;" ::: "memory");
        }
        asm volatile("cp.async.wait_group %0;" :: "n"(PF - 1) : "memory");
    }

    // ---- initial state ----
    float z = z0[(size_t)b * ND + i];
    sm_z[h][i] = z;
    __syncthreads();   // publishes ring stage 0 AND sm_z

    unsigned long long z2[16];
    {
        const unsigned long long* zz =
            reinterpret_cast<const unsigned long long*>(&sm_z[h][0]);
#pragma unroll
        for (int m = 0; m < 16; m++) z2[m] = zz[m];
    }

    float* yp = ys + (size_t)b * ND + i;

    for (int t = 0; t < NT; t++) {
        const int slot = t & (RING - 1);

        // ---- issue prefetch for stage t+PF (warp 0), commit every iter ----
        if (h == 0) {
            const int tp = t + PF;
            if (tp < NT) {
                const int ps = tp & (RING - 1);
                if (i < 8)
                    cp16(s_n + (uint32_t)(ps * ND + i * 4) * 4,
                         gn + (size_t)tp * NB * ND + i * 4);
                else if (i < 10)
                    cp16(s_w + (uint32_t)(ps * 8 + (i - 8) * 4) * 4,
                         gw + (size_t)tp * NB * NK + (i - 8) * 4);
            }
            asm volatile("cp.async.commit_group;" ::: "memory");
        }

        // ---- consume stage t (guaranteed complete & published last iter) ----
        const float4 wa = *reinterpret_cast<const float4*>(&sm_w[slot][0]);
        const float4 wb = *reinterpret_cast<const float4*>(&sm_w[slot][4]);
        const float  nz = sm_n[slot][i];

        // ---- 4 dot products (this warp's k-half), packed f32x2 ----
        unsigned long long acc0 = 0ull, acc1 = 0ull, acc2 = 0ull, acc3 = 0ull;
#pragma unroll
        for (int m = 0; m < 16; m++) {
            acc0 = ffma2(A2[0][m], z2[m], acc0);
            acc1 = ffma2(A2[1][m], z2[m], acc1);
            acc2 = ffma2(A2[2][m], z2[m], acc2);
            acc3 = ffma2(A2[3][m], z2[m], acc3);
        }
        float2 d0 = unpack2(acc0), d1 = unpack2(acc1);
        float2 d2 = unpack2(acc2), d3 = unpack2(acc3);
        const float dot0 = d0.x + d0.y;
        const float dot1 = d1.x + d1.y;
        const float dot2 = d2.x + d2.y;
        const float dot3 = d3.x + d3.y;

        const float wsum = ((wa.x + wa.y) + (wa.z + wa.w)) +
                           ((wb.x + wb.y) + (wb.z + wb.w));
        const float inv = __fdividef(1.0f, wsum);

        float wk0, wk1, wk2, wk3;
        if (h == 0) { wk0 = wa.x; wk1 = wa.y; wk2 = wa.z; wk3 = wa.w; }
        else        { wk0 = wb.x; wk1 = wb.y; wk2 = wb.z; wk3 = wb.w; }

        const float p = wk0 * (dot0 + breg[0]) + wk1 * (dot1 + breg[1]) +
                        wk2 * (dot2 + breg[2]) + wk3 * (dot3 + breg[3]);

        const float q = wa.x * Qreg[0] + wa.y * Qreg[1] + wa.z * Qreg[2] + wa.w * Qreg[3] +
                        wb.x * Qreg[4] + wb.y * Qreg[5] + wb.z * Qreg[6] + wb.w * Qreg[7];

        // ---- cross-warp combine; barrier also publishes ring stage t+1 ----
        sm_p[h][i] = p;
        if (h == 0)
            asm volatile("cp.async.wait_group %0;" :: "n"(PF - 1) : "memory");
        __syncthreads();
        const float psum = p + sm_p[1 - h][i];   // identical in both warps

        z = z + (DTC * inv) * psum + (q * inv) * (SQDT * nz);

        yp[(size_t)t * NB * ND] = z;

        // ---- intra-warp z broadcast (no CTA barrier needed) ----
        sm_z[h][i] = z;
        __syncwarp();
        const unsigned long long* zz =
            reinterpret_cast<const unsigned long long*>(&sm_z[h][0]);
#pragma unroll
        for (int m = 0; m < 16; m++) z2[m] = zz[m];
    }
}

extern "C" void kernel_launch(void* const* d_in, const int* in_sizes, int n_in,
                              void* d_out, int out_size) {
    const float* z0      = (const float*)d_in[0];
    const float* s_probs = (const float*)d_in[1];
    const float* noise   = (const float*)d_in[2];
    const float* A_s     = (const float*)d_in[3];
    const float* b_s     = (const float*)d_in[4];
    const float* Q_chol  = (const float*)d_in[5];
    float* ys = (float*)d_out;

    slds_scan_kernel<<<NB, 64>>>(z0, s_probs, noise, A_s, b_s, Q_chol, ys);
}